// round 16
// baseline (speedup 1.0000x reference)
#include <cuda_runtime.h>
#include <cuda_bf16.h>
#include <cstdint>

// ---------------- problem constants ----------------
#define LAYERS 4
#define NHEADS 4
#define H 64
#define DHD 16
#define FIN 32
#define ACT 15
#define OBSD 1500
#define HS 512
#define NOUTD 15
#define VHD 128
#define BATCH 128
#define NNODE 1000
#define TOTN (BATCH*NNODE)      // 128000
#define DEG 4
#define NEDGE (TOTN*DEG)        // 512000

#define BM 128
#define NB (TOTN/BM)            // 1000
#define NTHR 256                // 8 warps, warp = 16 rows x 64 cols (min smem traffic)

#define SA64 72                 // bf16-elem stride; conflict-free ldmatrix
#define A64_B   (128*SA64*2)    // 18432 per hi/lo component
#define B64_B   (64*SA64*2)     // 9216 per component
#define TILE_B  (2*B64_B)       // 18432

// fused-layer smem regions (bytes)
#define R_X   0                  // x hi/lo: 36864
#define R_B   36864              // weight tile hi/lo: 18432
#define R_H   55296              // agg A / sOut / hid hi/lo: 36864
#define SM_LAYER 92160           // 2 CTAs/SM

#define NTILES 33
#define SCAN_BLKS 125

// ---------------- scratch ----------------
__device__ __align__(16) float g_x[TOTN*H];
__device__ __align__(16) float g_q[TOTN*H];
__device__ __align__(16) float g_k[TOTN*H];
__device__ __align__(16) float g_v[TOTN*H];
__device__ __align__(16) float g_agg[TOTN*H];
__device__ __align__(16) char g_wimg[NTILES*TILE_B];
__device__ int g_deg[TOTN];
__device__ int g_rowptr[TOTN+1];
__device__ int g_cursor[TOTN];
__device__ int g_srcs[NEDGE];
__device__ int g_bsum[SCAN_BLKS];
__device__ int g_boff[SCAN_BLKS];

// ---------------- mma / ldmatrix primitives ----------------
__device__ __forceinline__ uint32_t smem_u32(const void* p){
    uint32_t a;
    asm("{ .reg .u64 t; cvta.to.shared.u64 t, %1; cvt.u32.u64 %0, t; }" : "=r"(a) : "l"(p));
    return a;
}
__device__ __forceinline__ void ldsm4(uint32_t* r, uint32_t addr){
    asm volatile("ldmatrix.sync.aligned.m8n8.x4.shared.b16 {%0,%1,%2,%3}, [%4];"
        : "=r"(r[0]),"=r"(r[1]),"=r"(r[2]),"=r"(r[3]) : "r"(addr));
}
__device__ __forceinline__ void mma4(float* c, const uint32_t* a, uint32_t b0, uint32_t b1){
    asm volatile("mma.sync.aligned.m16n8k16.row.col.f32.bf16.bf16.f32 "
        "{%0,%1,%2,%3}, {%4,%5,%6,%7}, {%8,%9}, {%0,%1,%2,%3};"
        : "+f"(c[0]),"+f"(c[1]),"+f"(c[2]),"+f"(c[3])
        : "r"(a[0]),"r"(a[1]),"r"(a[2]),"r"(a[3]), "r"(b0),"r"(b1));
}
__device__ __forceinline__ void pack2(float v0, float v1, uint32_t& hp, uint32_t& lp){
    __nv_bfloat16 h0 = __float2bfloat16(v0), h1 = __float2bfloat16(v1);
    float r0 = v0 - __bfloat162float(h0), r1 = v1 - __bfloat162float(h1);
    __nv_bfloat16 l0 = __float2bfloat16(r0), l1 = __float2bfloat16(r1);
    hp = ((uint32_t)__bfloat16_as_ushort(h1) << 16) | __bfloat16_as_ushort(h0);
    lp = ((uint32_t)__bfloat16_as_ushort(l1) << 16) | __bfloat16_as_ushort(l0);
}

template<int KC>
__device__ __forceinline__ void stage_A(const float* __restrict__ g, int rs,
                                        char* hi, char* lo, int tid){
    for (int idx = tid; idx < 128*(KC/8); idx += NTHR){
        int row = idx / (KC/8), c8 = (idx % (KC/8)) * 8;
        float4 f0 = *(const float4*)(g + (size_t)row*rs + c8);
        float4 f1 = *(const float4*)(g + (size_t)row*rs + c8 + 4);
        float v[8] = {f0.x,f0.y,f0.z,f0.w,f1.x,f1.y,f1.z,f1.w};
        uint32_t hp[4], lp[4];
#pragma unroll
        for (int j = 0; j < 4; j++) pack2(v[2*j], v[2*j+1], hp[j], lp[j]);
        *(uint4*)(hi + row*SA64*2 + c8*2) = make_uint4(hp[0],hp[1],hp[2],hp[3]);
        *(uint4*)(lo + row*SA64*2 + c8*2) = make_uint4(lp[0],lp[1],lp[2],lp[3]);
    }
}
__device__ __forceinline__ void stage_Bimg(int tile, char* Bhi, int tid){
    const uint4* s = (const uint4*)(g_wimg + (size_t)tile * TILE_B);
    uint4* d = (uint4*)Bhi;
    for (int i = tid; i < TILE_B/16; i += NTHR) d[i] = s[i];
}

// warp mma: 16 rows x 64 cols, KS k16-steps, hi/lo 3-term
template<int KS>
__device__ __forceinline__ void mma_loop(const char* A_hi, const char* A_lo,
                                         const char* B_hi, const char* B_lo,
                                         int lane, int m0, float acc[][4]){
    int q = lane >> 3, r = lane & 7;
    uint32_t aoff = (uint32_t)(m0 + ((q & 1) << 3) + r) * (SA64*2) + (((q >> 1) << 3) * 2);
    uint32_t ah = smem_u32(A_hi) + aoff, al = smem_u32(A_lo) + aoff;
    uint32_t boff = (uint32_t)(((q >> 1) << 3) + r) * (SA64*2) + (((q & 1) << 3) * 2);
    uint32_t bh0 = smem_u32(B_hi) + boff, bl0 = smem_u32(B_lo) + boff;
#pragma unroll
    for (int kk = 0; kk < KS; kk++){
        uint32_t af[4], alf[4];
        ldsm4(af,  ah + kk*32);
        ldsm4(alf, al + kk*32);
#pragma unroll
        for (int g2 = 0; g2 < 4; g2++){
            uint32_t bf[4], blf[4];
            ldsm4(bf,  bh0 + g2*16*(SA64*2) + kk*32);
            ldsm4(blf, bl0 + g2*16*(SA64*2) + kk*32);
            mma4(acc[g2*2],   af,  bf[0],  bf[1]);
            mma4(acc[g2*2+1], af,  bf[2],  bf[3]);
            mma4(acc[g2*2],   af,  blf[0], blf[1]);
            mma4(acc[g2*2+1], af,  blf[2], blf[3]);
            mma4(acc[g2*2],   alf, bf[0],  bf[1]);
            mma4(acc[g2*2+1], alf, bf[2],  bf[3]);
        }
    }
}
__device__ __forceinline__ void zero8(float acc[][4]){
#pragma unroll
    for (int i = 0; i < 8; i++){ acc[i][0]=0; acc[i][1]=0; acc[i][2]=0; acc[i][3]=0; }
}
__device__ __forceinline__ void store_frags8(float* __restrict__ g, int rs, int m0,
                                             int lane, float acc[][4]){
    int r = lane >> 2, c2 = (lane & 3) * 2;
#pragma unroll
    for (int nt = 0; nt < 8; nt++){
        int col = nt*8 + c2;
        *(float2*)(g + (size_t)(m0+r)*rs + col)   = make_float2(acc[nt][0], acc[nt][1]);
        *(float2*)(g + (size_t)(m0+r+8)*rs + col) = make_float2(acc[nt][2], acc[nt][3]);
    }
}
__device__ __forceinline__ void stage_frags8(float* sOut, int m0, int lane, float acc[][4]){
    int r = lane >> 2, c2 = (lane & 3) * 2;
#pragma unroll
    for (int nt = 0; nt < 8; nt++){
        int col = nt*8 + c2;
        *(float2*)(sOut + (m0+r)*66 + col)   = make_float2(acc[nt][0], acc[nt][1]);
        *(float2*)(sOut + (m0+r+8)*66 + col) = make_float2(acc[nt][2], acc[nt][3]);
    }
}
// coalesced row writer: thread=row, 64 floats as 16 float4 (sOut stride 66 -> read float2 pairs)
__device__ __forceinline__ void rows_to_global(const float* sOut, float* __restrict__ g,
                                               int node0, int tid){
    if (tid < 128){
        const float* src = sOut + tid*66;
        float* dst = g + (size_t)(node0 + tid) * H;
#pragma unroll
        for (int c = 0; c < 16; c++){
            float2 a = *(const float2*)(src + 4*c);
            float2 b = *(const float2*)(src + 4*c + 2);
            *(float4*)(dst + 4*c) = make_float4(a.x, a.y, b.x, b.y);
        }
    }
}
__device__ __forceinline__ void frag_relu_pack(char* Hhi, char* Hlo, int m0, int lane,
                                               float acc[][4], const float* __restrict__ bias){
    int r = lane >> 2, c2 = (lane & 3) * 2;
#pragma unroll
    for (int nt = 0; nt < 8; nt++){
        int col = nt*8 + c2;
        float b0 = __ldg(bias+col), b1 = __ldg(bias+col+1);
        float v0 = fmaxf(acc[nt][0]+b0, 0.f), v1 = fmaxf(acc[nt][1]+b1, 0.f);
        float v2 = fmaxf(acc[nt][2]+b0, 0.f), v3 = fmaxf(acc[nt][3]+b1, 0.f);
        uint32_t hp, lp;
        pack2(v0, v1, hp, lp);
        *(uint32_t*)(Hhi + (m0+r)*SA64*2 + col*2) = hp;
        *(uint32_t*)(Hlo + (m0+r)*SA64*2 + col*2) = lp;
        pack2(v2, v3, hp, lp);
        *(uint32_t*)(Hhi + (m0+r+8)*SA64*2 + col*2) = hp;
        *(uint32_t*)(Hlo + (m0+r+8)*SA64*2 + col*2) = lp;
    }
}
__device__ __forceinline__ void ln_pack_row(const float* sOut, int node, int row,
                                            const float* __restrict__ bias,
                                            const float* __restrict__ lg,
                                            const float* __restrict__ lb,
                                            char* Xhi, char* Xlo){
    float o[H];
#pragma unroll
    for (int i = 0; i < H; i++) o[i] = sOut[row*66 + i];
    const float4* xp = (const float4*)(g_x + (size_t)node * H);
#pragma unroll
    for (int i = 0; i < 16; i++){
        float4 f = xp[i];
        o[4*i+0] += f.x; o[4*i+1] += f.y; o[4*i+2] += f.z; o[4*i+3] += f.w;
    }
    if (bias){
#pragma unroll
        for (int i = 0; i < H; i++) o[i] += __ldg(&bias[i]);
    }
    float mean = 0.f;
#pragma unroll
    for (int i = 0; i < H; i++) mean += o[i];
    mean *= (1.f / H);
    float var = 0.f;
#pragma unroll
    for (int i = 0; i < H; i++){ float d = o[i] - mean; var += d * d; }
    var *= (1.f / H);
    float rr = rsqrtf(var + 1e-5f);
    float g[H];
#pragma unroll
    for (int i = 0; i < H; i++)
        g[i] = (o[i]-mean)*rr*__ldg(&lg[i]) + __ldg(&lb[i]);
    float4* op = (float4*)(g_x + (size_t)node * H);
#pragma unroll
    for (int i = 0; i < 16; i++)
        op[i] = make_float4(g[4*i+0], g[4*i+1], g[4*i+2], g[4*i+3]);
#pragma unroll
    for (int i = 0; i < 32; i++){
        uint32_t hp, lp;
        pack2(g[2*i], g[2*i+1], hp, lp);
        *(uint32_t*)(Xhi + row*SA64*2 + i*4) = hp;
        *(uint32_t*)(Xlo + row*SA64*2 + i*4) = lp;
    }
}
__device__ __forceinline__ void row_store_pack(const float* sOut, int node, int row,
                                               char* Xhi, char* Xlo){
    float g[H];
#pragma unroll
    for (int i = 0; i < H; i++) g[i] = sOut[row*66 + i];
    float4* op = (float4*)(g_x + (size_t)node * H);
#pragma unroll
    for (int i = 0; i < 16; i++)
        op[i] = make_float4(g[4*i+0], g[4*i+1], g[4*i+2], g[4*i+3]);
#pragma unroll
    for (int i = 0; i < 32; i++){
        uint32_t hp, lp;
        pack2(g[2*i], g[2*i+1], hp, lp);
        *(uint32_t*)(Xhi + row*SA64*2 + i*4) = hp;
        *(uint32_t*)(Xlo + row*SA64*2 + i*4) = lp;
    }
}
// qkv via sOut-staged coalesced stores. sOut region (R_H) must be free.
__device__ __forceinline__ void qkv_st(char* Xhi, char* Xlo, char* B0, float* sOut,
                                       int t0, int node0, int wid, int lane, int tid){
    float* outs[3] = { g_q, g_k, g_v };
#pragma unroll
    for (int m = 0; m < 3; m++){
        __syncthreads();                 // sOut rows consumed / prev B free / X visible (m==0)
        stage_Bimg(t0 + m, B0, tid);
        __syncthreads();
        float acc[8][4]; zero8(acc);
        mma_loop<4>(Xhi, Xlo, B0, B0 + B64_B, lane, wid*16, acc);
        stage_frags8(sOut, wid*16, lane, acc);   // disjoint per-warp regions
        __syncthreads();
        rows_to_global(sOut, outs[m] + 0, node0, tid);
    }
}

// ---------------- weight prep ----------------
__global__ void k_prep(const float* __restrict__ Win, const float* __restrict__ Wq,
                       const float* __restrict__ Wk, const float* __restrict__ Wv,
                       const float* __restrict__ Wo, const float* __restrict__ W1,
                       const float* __restrict__ W2){
    int t = blockIdx.x;
    const float* src; int ns, Ksrc;
    if (t == 0){ src = Win; ns = 64; Ksrc = FIN; }
    else {
        int l = (t-1)/8, j = (t-1)%8;
        if (j < 3){ const float* ws[3] = {Wq,Wk,Wv}; src = ws[j] + l*H*H; ns = 64; Ksrc = 64; }
        else if (j == 3){ src = Wo + l*H*H; ns = 64; Ksrc = 64; }
        else if (j < 6){ src = W1 + l*H*2*H + (j-4)*64; ns = 128; Ksrc = 64; }
        else { src = W2 + l*2*H*H + (j-6)*64*64; ns = 64; Ksrc = 64; }
    }
    char* dst = g_wimg + (size_t)t * TILE_B;
    for (int idx = threadIdx.x; idx < 64*32; idx += 256){
        int n = idx >> 5, p = idx & 31, k = 2*p;
        float v0 = (k   < Ksrc) ? __ldg(src + (size_t)k*ns + n)     : 0.f;
        float v1 = (k+1 < Ksrc) ? __ldg(src + (size_t)(k+1)*ns + n) : 0.f;
        uint32_t hp, lp;
        pack2(v0, v1, hp, lp);
        *(uint32_t*)(dst + n*SA64*2 + k*2) = hp;
        *(uint32_t*)(dst + B64_B + n*SA64*2 + k*2) = lp;
    }
}

// ---------------- CSR build (parallel scan) ----------------
__global__ void k_zero_deg(){
    int i = blockIdx.x * 256 + threadIdx.x;
    if (i < TOTN) g_deg[i] = 0;
}
__global__ void k_hist(const int* __restrict__ edst){
    int e = blockIdx.x * 256 + threadIdx.x;
    if (e < NEDGE) atomicAdd(&g_deg[edst[e]], 1);
}
__global__ __launch_bounds__(1024) void k_scan1(){
    __shared__ int s[1024];
    int tid = threadIdx.x;
    int i = blockIdx.x * 1024 + tid;
    int d = g_deg[i];
    s[tid] = d;
    __syncthreads();
#pragma unroll
    for (int off = 1; off < 1024; off <<= 1){
        int v = (tid >= off) ? s[tid - off] : 0;
        __syncthreads();
        s[tid] += v;
        __syncthreads();
    }
    g_rowptr[i] = s[tid] - d;
    if (tid == 1023) g_bsum[blockIdx.x] = s[1023];
}
__global__ void k_scan2(){
    if (threadIdx.x == 0){
        int run = 0;
        for (int b = 0; b < SCAN_BLKS; b++){ g_boff[b] = run; run += g_bsum[b]; }
        g_rowptr[TOTN] = run;
    }
}
__global__ __launch_bounds__(1024) void k_scan3(){
    int i = blockIdx.x * 1024 + threadIdx.x;
    int v = g_rowptr[i] + g_boff[blockIdx.x];
    g_rowptr[i] = v;
    g_cursor[i] = v;
}
__global__ void k_scatter(const int* __restrict__ esrc, const int* __restrict__ edst){
    int e = blockIdx.x * 256 + threadIdx.x;
    if (e < NEDGE){
        int d = edst[e];
        int pos = atomicAdd(&g_cursor[d], 1);
        g_srcs[pos] = esrc[e];
    }
}

// ---------------- fused input + layer-0 qkv ----------------
__global__ __launch_bounds__(NTHR) void k_in_qkv(const float* __restrict__ nf){
    extern __shared__ __align__(16) char sm[];
    char* Xhi = sm + R_X;  char* Xlo = Xhi + A64_B;
    char* B0  = sm + R_B;
    char* Hhi = sm + R_H;  char* Hlo = Hhi + A64_B;
    int tid = threadIdx.x, wid = tid >> 5, lane = tid & 31;
    int node0 = blockIdx.x * BM;

    stage_A<FIN>(nf + (size_t)node0 * FIN, FIN, Hhi, Hlo, tid);
    stage_Bimg(0, B0, tid);
    __syncthreads();
    float acc[8][4]; zero8(acc);
    mma_loop<2>(Hhi, Hlo, B0, B0 + B64_B, lane, wid*16, acc);
    __syncthreads();
    float* sOut = (float*)(sm + R_H);
    stage_frags8(sOut, wid*16, lane, acc);
    __syncthreads();
    if (tid < 128) row_store_pack(sOut, node0 + tid, tid, Xhi, Xlo);

    qkv_st(Xhi, Xlo, B0, sOut, 1, node0, wid, lane, tid);
}

// ---------------- fused layer ----------------
__global__ __launch_bounds__(NTHR) void k_layer(int l,
                                                const float* __restrict__ lg1,
                                                const float* __restrict__ lb1,
                                                const float* __restrict__ b1,
                                                const float* __restrict__ b2,
                                                const float* __restrict__ lg2,
                                                const float* __restrict__ lb2,
                                                int last){
    extern __shared__ __align__(16) char sm[];
    char* Xhi = sm + R_X;  char* Xlo = Xhi + A64_B;
    char* B0  = sm + R_B;
    char* Hhi = sm + R_H;  char* Hlo = Hhi + A64_B;
    int tid = threadIdx.x, wid = tid >> 5, lane = tid & 31;
    int node0 = blockIdx.x * BM;
    int tb = 1 + l*8;

    // phase 1: attn_out = agg @ Wo ; x = LN1(x + attn_out)
    stage_A<H>(g_agg + (size_t)node0 * H, H, Hhi, Hlo, tid);
    stage_Bimg(tb + 3, B0, tid);
    __syncthreads();
    {
        float acc[8][4]; zero8(acc);
        mma_loop<4>(Hhi, Hlo, B0, B0 + B64_B, lane, wid*16, acc);
        __syncthreads();
        float* sOut = (float*)(sm + R_H);
        stage_frags8(sOut, wid*16, lane, acc);
        __syncthreads();
        if (tid < 128) ln_pack_row(sOut, node0 + tid, tid, nullptr, lg1, lb1, Xhi, Xlo);
        __syncthreads();
    }

    // phase 2: interleaved FFN1 halves + FFN2 K-chunks; hid stays in smem
    float acc2[8][4]; zero8(acc2);
#pragma unroll
    for (int h = 0; h < 2; h++){
        stage_Bimg(tb + 4 + h, B0, tid);
        __syncthreads();
        float acc1[8][4]; zero8(acc1);
        mma_loop<4>(Xhi, Xlo, B0, B0 + B64_B, lane, wid*16, acc1);
        __syncthreads();
        frag_relu_pack(Hhi, Hlo, wid*16, lane, acc1, b1 + h*64);
        stage_Bimg(tb + 6 + h, B0, tid);
        __syncthreads();
        mma_loop<4>(Hhi, Hlo, B0, B0 + B64_B, lane, wid*16, acc2);
        __syncthreads();
    }
    // phase 3: x = LN2(x + h@W2 + b2)
    {
        float* sOut = (float*)(sm + R_H);
        stage_frags8(sOut, wid*16, lane, acc2);
        __syncthreads();
        if (tid < 128) ln_pack_row(sOut, node0 + tid, tid, b2, lg2, lb2, Xhi, Xlo);
    }
    // phase 4: qkv for next layer (sOut-staged coalesced stores)
    if (!last)
        qkv_st(Xhi, Xlo, B0, (float*)(sm + R_H), tb + 8, node0, wid, lane, tid);
}

// ---------------- warp-per-node attention (online softmax) ----------------
__global__ __launch_bounds__(256) void k_attn(){
    int warp = (blockIdx.x * 256 + threadIdx.x) >> 5;
    int lane = threadIdx.x & 31;
    if (warp >= TOTN) return;
    int node = warp;
    float2 q = *(const float2*)(g_q + (size_t)node * H + 2*lane);
    int s0 = g_rowptr[node], s1 = g_rowptr[node + 1];
    float m = -1e30f, den = 0.f, ax = 0.f, ay = 0.f;
    for (int e = s0; e < s1; e++){
        int src = g_srcs[e];
        float2 kk = *(const float2*)(g_k + (size_t)src * H + 2*lane);
        float2 vv = *(const float2*)(g_v + (size_t)src * H + 2*lane);
        float p = q.x * kk.x + q.y * kk.y;
        p += __shfl_xor_sync(0xffffffffu, p, 1);
        p += __shfl_xor_sync(0xffffffffu, p, 2);
        p += __shfl_xor_sync(0xffffffffu, p, 4);
        float s = p * 0.25f;
        float mn = fmaxf(m, s);
        float scale = __expf(m - mn);
        float w = __expf(s - mn);
        den = den * scale + w;
        ax = ax * scale + w * vv.x;
        ay = ay * scale + w * vv.y;
        m = mn;
    }
    float inv = 1.f / (den + 1e-9f);
    *(float2*)(g_agg + (size_t)node * H + 2*lane) = make_float2(ax * inv, ay * inv);
}

// ---------------- merged heads ----------------
__global__ __launch_bounds__(512) void k_heads(const int* __restrict__ an,
                                               const float* __restrict__ obs,
                                               const float* __restrict__ Wr,  const float* __restrict__ br,
                                               const float* __restrict__ Wp1, const float* __restrict__ bp1,
                                               const float* __restrict__ Wp2, const float* __restrict__ bp2,
                                               const float* __restrict__ Wlog,const float* __restrict__ blog,
                                               const float* __restrict__ Wv1, const float* __restrict__ bv1,
                                               const float* __restrict__ Wv2, const float* __restrict__ bv2,
                                               const float* __restrict__ Wvo, const float* __restrict__ bvo,
                                               float* __restrict__ out){
    __shared__ float sr[ACT + OBSD];
    __shared__ float sx[H];
    __shared__ float sfeat[HS];
    __shared__ float svh[VHD];
    __shared__ float sval[1];
    int b = blockIdx.x;
    int tid = threadIdx.x;

    if (tid == 0) sval[0] = 0.f;          // init before first barrier
    if (tid < H) sx[tid] = g_x[(size_t)an[b] * H + tid];
    for (int i = tid; i < OBSD; i += 512) sr[ACT + i] = obs[(size_t)b * OBSD + i];
    __syncthreads();
    if (tid < ACT){
        float acc = br[tid];
        for (int i = 0; i < H; i++) acc += sx[i] * __ldg(&Wr[i*ACT + tid]);
        sr[tid] = acc;
    }
    __syncthreads();
    if (tid < VHD){
        const float* W = Wv1 + tid;
        float a0 = 0, a1 = 0, a2 = 0, a3 = 0;
        for (int i = 0; i < OBSD; i += 4){
            a0 += sr[ACT+i+0] * W[(size_t)(i+0)*VHD];
            a1 += sr[ACT+i+1] * W[(size_t)(i+1)*VHD];
            a2 += sr[ACT+i+2] * W[(size_t)(i+2)*VHD];
            a3 += sr[ACT+i+3] * W[(size_t)(i+3)*VHD];
        }
        svh[tid] = tanhf(a0 + a1 + a2 + a3 + bv1[tid]);
    }
    {
        int j = tid;
        const float* W = Wp1 + j;
        float a0 = 0, a1 = 0, a2 = 0, a3 = 0;
        int i = 0;
        const int K = ACT + OBSD;
        for (; i + 3 < K; i += 4){
            a0 += sr[i+0] * W[(size_t)(i+0)*HS];
            a1 += sr[i+1] * W[(size_t)(i+1)*HS];
            a2 += sr[i+2] * W[(size_t)(i+2)*HS];
            a3 += sr[i+3] * W[(size_t)(i+3)*HS];
        }
        for (; i < K; i++) a0 += sr[i] * W[(size_t)i*HS];
        float f = tanhf(a0 + a1 + a2 + a3 + bp1[j]);
        __syncthreads();
        sfeat[j] = f;
    }
    __syncthreads();
    if (tid < VHD){
        const float* W = Wv2 + tid;
        float a0 = 0, a1 = 0, a2 = 0, a3 = 0;
        for (int i = 0; i < VHD; i += 4){
            a0 += svh[i+0] * W[(i+0)*VHD];
            a1 += svh[i+1] * W[(i+1)*VHD];
            a2 += svh[i+2] * W[(i+2)*VHD];
            a3 += svh[i+3] * W[(i+3)*VHD];
        }
        float vh2 = tanhf(a0 + a1 + a2 + a3 + bv2[tid]);
        float p = vh2 * __ldg(&Wvo[tid]);
        p += __shfl_xor_sync(0xffffffffu, p, 1);
        p += __shfl_xor_sync(0xffffffffu, p, 2);
        p += __shfl_xor_sync(0xffffffffu, p, 4);
        p += __shfl_xor_sync(0xffffffffu, p, 8);
        p += __shfl_xor_sync(0xffffffffu, p, 16);
        if ((tid & 31) == 0) atomicAdd(&sval[0], p);
    }
    {
        int j = tid;
        const float* W = Wp2 + j;
        float a0 = 0, a1 = 0, a2 = 0, a3 = 0;
        for (int i = 0; i < HS; i += 4){
            a0 += sfeat[i+0] * W[(size_t)(i+0)*HS];
            a1 += sfeat[i+1] * W[(size_t)(i+1)*HS];
            a2 += sfeat[i+2] * W[(size_t)(i+2)*HS];
            a3 += sfeat[i+3] * W[(size_t)(i+3)*HS];
        }
        float f2 = tanhf(a0 + a1 + a2 + a3 + bp2[j]);
        __syncthreads();
        sfeat[j] = f2;
    }
    __syncthreads();
    if (tid < NOUTD){
        float acc = blog[tid];
        for (int i = 0; i < HS; i++) acc += sfeat[i] * __ldg(&Wlog[i*NOUTD + tid]);
        out[b*NOUTD + tid] = acc;
    }
    if (tid == 0) out[BATCH*NOUTD + b] = sval[0] + bvo[0];
}

// ---------------- launch ----------------
extern "C" void kernel_launch(void* const* d_in, const int* in_sizes, int n_in,
                              void* d_out, int out_size){
    const float* node_feats = (const float*)d_in[0];
    const float* obs        = (const float*)d_in[1];
    const int*   edge_src   = (const int*)  d_in[2];
    const int*   edge_dst   = (const int*)  d_in[3];
    const int*   agent      = (const int*)  d_in[4];
    const float* W_in  = (const float*)d_in[5];
    const float* Wq    = (const float*)d_in[6];
    const float* Wk    = (const float*)d_in[7];
    const float* Wv    = (const float*)d_in[8];
    const float* Wo    = (const float*)d_in[9];
    const float* ln1g  = (const float*)d_in[10];
    const float* ln1b  = (const float*)d_in[11];
    const float* W1    = (const float*)d_in[12];
    const float* b1    = (const float*)d_in[13];
    const float* W2    = (const float*)d_in[14];
    const float* b2    = (const float*)d_in[15];
    const float* ln2g  = (const float*)d_in[16];
    const float* ln2b  = (const float*)d_in[17];
    const float* Wr    = (const float*)d_in[18];
    const float* br    = (const float*)d_in[19];
    const float* Wp1   = (const float*)d_in[20];
    const float* bp1   = (const float*)d_in[21];
    const float* Wp2   = (const float*)d_in[22];
    const float* bp2   = (const float*)d_in[23];
    const float* Wlog  = (const float*)d_in[24];
    const float* blog  = (const float*)d_in[25];
    const float* Wv1   = (const float*)d_in[26];
    const float* bv1   = (const float*)d_in[27];
    const float* Wv2   = (const float*)d_in[28];
    const float* bv2   = (const float*)d_in[29];
    const float* Wvo   = (const float*)d_in[30];
    const float* bvo   = (const float*)d_in[31];
    float* out = (float*)d_out;

    cudaFuncSetAttribute((const void*)k_in_qkv, cudaFuncAttributeMaxDynamicSharedMemorySize, SM_LAYER);
    cudaFuncSetAttribute((const void*)k_layer,  cudaFuncAttributeMaxDynamicSharedMemorySize, SM_LAYER);

    k_prep<<<NTILES, 256>>>(W_in, Wq, Wk, Wv, Wo, W1, W2);
    k_zero_deg<<<(TOTN + 255)/256, 256>>>();
    k_hist<<<(NEDGE + 255)/256, 256>>>(edge_dst);
    k_in_qkv<<<NB, NTHR, SM_LAYER>>>(node_feats);      // capture slot (index 3)
    k_scan1<<<SCAN_BLKS, 1024>>>();
    k_scan2<<<1, 32>>>();
    k_scan3<<<SCAN_BLKS, 1024>>>();
    k_scatter<<<(NEDGE + 255)/256, 256>>>(edge_src, edge_dst);

    for (int l = 0; l < LAYERS; l++){
        k_attn<<<(TOTN*32 + 255)/256, 256>>>();
        k_layer<<<NB, NTHR, SM_LAYER>>>(l, ln1g + l*H, ln1b + l*H,
                                        b1 + l*2*H, b2 + l*H,
                                        ln2g + l*H, ln2b + l*H,
                                        (l == LAYERS-1) ? 1 : 0);
    }

    k_heads<<<BATCH, 512>>>(agent, obs, Wr, br, Wp1, bp1, Wp2, bp2,
                            Wlog, blog, Wv1, bv1, Wv2, bv2, Wvo, bvo, out);
}

// round 17
// speedup vs baseline: 1.2494x; 1.2494x over previous
#include <cuda_runtime.h>
#include <cuda_bf16.h>
#include <cstdint>

// ---------------- problem constants ----------------
#define LAYERS 4
#define NHEADS 4
#define H 64
#define DHD 16
#define FIN 32
#define ACT 15
#define OBSD 1500
#define HS 512
#define NOUTD 15
#define VHD 128
#define BATCH 128
#define NNODE 1000
#define TOTN (BATCH*NNODE)      // 128000
#define DEG 4
#define NEDGE (TOTN*DEG)        // 512000

#define BM 128
#define NB (TOTN/BM)            // 1000
#define NTHR 256                // 8 warps, warp = 16 rows x 64 cols

#define SA64 72                 // bf16-elem stride; conflict-free ldmatrix
#define A64_B   (128*SA64*2)    // 18432 per hi/lo component
#define B64_B   (64*SA64*2)     // 9216 per component
#define TILE_B  (2*B64_B)       // 18432
#define PF_N 5                  // 1152 uint4 / 256 thr

// fused-layer smem regions (bytes)
#define R_X   0                  // x hi/lo: 36864
#define R_B0  36864              // weight tile buffer 0: 18432
#define R_H   55296              // agg A / sOut / hid hi/lo: 36864
#define R_B1  92160              // weight tile buffer 1: 18432
#define SM_LAYER 110592          // 2 CTAs/SM (221KB < 228KB)

#define NTILES 33
#define SCAN_BLKS 125

// ---------------- scratch ----------------
__device__ __align__(16) float g_x[TOTN*H];
__device__ __align__(16) float g_q[TOTN*H];
__device__ __align__(16) float g_k[TOTN*H];
__device__ __align__(16) float g_v[TOTN*H];
__device__ __align__(16) float g_agg[TOTN*H];
__device__ __align__(16) char g_wimg[NTILES*TILE_B];
__device__ int g_deg[TOTN];
__device__ int g_rowptr[TOTN+1];
__device__ int g_cursor[TOTN];
__device__ int g_srcs[NEDGE];
__device__ int g_bsum[SCAN_BLKS];
__device__ int g_boff[SCAN_BLKS];

// ---------------- mma / ldmatrix primitives ----------------
__device__ __forceinline__ uint32_t smem_u32(const void* p){
    uint32_t a;
    asm("{ .reg .u64 t; cvta.to.shared.u64 t, %1; cvt.u32.u64 %0, t; }" : "=r"(a) : "l"(p));
    return a;
}
__device__ __forceinline__ void ldsm4(uint32_t* r, uint32_t addr){
    asm volatile("ldmatrix.sync.aligned.m8n8.x4.shared.b16 {%0,%1,%2,%3}, [%4];"
        : "=r"(r[0]),"=r"(r[1]),"=r"(r[2]),"=r"(r[3]) : "r"(addr));
}
__device__ __forceinline__ void mma4(float* c, const uint32_t* a, uint32_t b0, uint32_t b1){
    asm volatile("mma.sync.aligned.m16n8k16.row.col.f32.bf16.bf16.f32 "
        "{%0,%1,%2,%3}, {%4,%5,%6,%7}, {%8,%9}, {%0,%1,%2,%3};"
        : "+f"(c[0]),"+f"(c[1]),"+f"(c[2]),"+f"(c[3])
        : "r"(a[0]),"r"(a[1]),"r"(a[2]),"r"(a[3]), "r"(b0),"r"(b1));
}
__device__ __forceinline__ void pack2(float v0, float v1, uint32_t& hp, uint32_t& lp){
    __nv_bfloat16 h0 = __float2bfloat16(v0), h1 = __float2bfloat16(v1);
    float r0 = v0 - __bfloat162float(h0), r1 = v1 - __bfloat162float(h1);
    __nv_bfloat16 l0 = __float2bfloat16(r0), l1 = __float2bfloat16(r1);
    hp = ((uint32_t)__bfloat16_as_ushort(h1) << 16) | __bfloat16_as_ushort(h0);
    lp = ((uint32_t)__bfloat16_as_ushort(l1) << 16) | __bfloat16_as_ushort(l0);
}

template<int KC>
__device__ __forceinline__ void stage_A(const float* __restrict__ g, int rs,
                                        char* hi, char* lo, int tid){
    for (int idx = tid; idx < 128*(KC/8); idx += NTHR){
        int row = idx / (KC/8), c8 = (idx % (KC/8)) * 8;
        float4 f0 = *(const float4*)(g + (size_t)row*rs + c8);
        float4 f1 = *(const float4*)(g + (size_t)row*rs + c8 + 4);
        float v[8] = {f0.x,f0.y,f0.z,f0.w,f1.x,f1.y,f1.z,f1.w};
        uint32_t hp[4], lp[4];
#pragma unroll
        for (int j = 0; j < 4; j++) pack2(v[2*j], v[2*j+1], hp[j], lp[j]);
        *(uint4*)(hi + row*SA64*2 + c8*2) = make_uint4(hp[0],hp[1],hp[2],hp[3]);
        *(uint4*)(lo + row*SA64*2 + c8*2) = make_uint4(lp[0],lp[1],lp[2],lp[3]);
    }
}
__device__ __forceinline__ void stage_Bimg(int tile, char* B, int tid){
    const uint4* s = (const uint4*)(g_wimg + (size_t)tile * TILE_B);
    uint4* d = (uint4*)B;
    for (int i = tid; i < TILE_B/16; i += NTHR) d[i] = s[i];
}
// register-staged prefetch: loads issue early, stores drain after mma
__device__ __forceinline__ void pref_ld(int tile, uint4* r, int tid){
    const uint4* s = (const uint4*)(g_wimg + (size_t)tile * TILE_B);
#pragma unroll
    for (int i = 0; i < PF_N; i++){
        int idx = tid + i*NTHR;
        if (idx < TILE_B/16) r[i] = s[idx];
    }
}
__device__ __forceinline__ void pref_st(char* B, const uint4* r, int tid){
    uint4* d = (uint4*)B;
#pragma unroll
    for (int i = 0; i < PF_N; i++){
        int idx = tid + i*NTHR;
        if (idx < TILE_B/16) d[idx] = r[i];
    }
}

// warp mma: 16 rows x 64 cols, KS k16-steps, hi/lo 3-term
template<int KS>
__device__ __forceinline__ void mma_loop(const char* A_hi, const char* A_lo,
                                         const char* B, int lane, int m0, float acc[][4]){
    const char* B_hi = B;
    const char* B_lo = B + B64_B;
    int q = lane >> 3, r = lane & 7;
    uint32_t aoff = (uint32_t)(m0 + ((q & 1) << 3) + r) * (SA64*2) + (((q >> 1) << 3) * 2);
    uint32_t ah = smem_u32(A_hi) + aoff, al = smem_u32(A_lo) + aoff;
    uint32_t boff = (uint32_t)(((q >> 1) << 3) + r) * (SA64*2) + (((q & 1) << 3) * 2);
    uint32_t bh0 = smem_u32(B_hi) + boff, bl0 = smem_u32(B_lo) + boff;
#pragma unroll
    for (int kk = 0; kk < KS; kk++){
        uint32_t af[4], alf[4];
        ldsm4(af,  ah + kk*32);
        ldsm4(alf, al + kk*32);
#pragma unroll
        for (int g2 = 0; g2 < 4; g2++){
            uint32_t bf[4], blf[4];
            ldsm4(bf,  bh0 + g2*16*(SA64*2) + kk*32);
            ldsm4(blf, bl0 + g2*16*(SA64*2) + kk*32);
            mma4(acc[g2*2],   af,  bf[0],  bf[1]);
            mma4(acc[g2*2+1], af,  bf[2],  bf[3]);
            mma4(acc[g2*2],   af,  blf[0], blf[1]);
            mma4(acc[g2*2+1], af,  blf[2], blf[3]);
            mma4(acc[g2*2],   alf, bf[0],  bf[1]);
            mma4(acc[g2*2+1], alf, bf[2],  bf[3]);
        }
    }
}
__device__ __forceinline__ void zero8(float acc[][4]){
#pragma unroll
    for (int i = 0; i < 8; i++){ acc[i][0]=0; acc[i][1]=0; acc[i][2]=0; acc[i][3]=0; }
}
__device__ __forceinline__ void store_frags8(float* __restrict__ g, int rs, int m0,
                                             int lane, float acc[][4]){
    int r = lane >> 2, c2 = (lane & 3) * 2;
#pragma unroll
    for (int nt = 0; nt < 8; nt++){
        int col = nt*8 + c2;
        *(float2*)(g + (size_t)(m0+r)*rs + col)   = make_float2(acc[nt][0], acc[nt][1]);
        *(float2*)(g + (size_t)(m0+r+8)*rs + col) = make_float2(acc[nt][2], acc[nt][3]);
    }
}
__device__ __forceinline__ void stage_frags8(float* sOut, int m0, int lane, float acc[][4]){
    int r = lane >> 2, c2 = (lane & 3) * 2;
#pragma unroll
    for (int nt = 0; nt < 8; nt++){
        int col = nt*8 + c2;
        *(float2*)(sOut + (m0+r)*66 + col)   = make_float2(acc[nt][0], acc[nt][1]);
        *(float2*)(sOut + (m0+r+8)*66 + col) = make_float2(acc[nt][2], acc[nt][3]);
    }
}
__device__ __forceinline__ void frag_relu_pack(char* Hhi, char* Hlo, int m0, int lane,
                                               float acc[][4], const float* __restrict__ bias){
    int r = lane >> 2, c2 = (lane & 3) * 2;
#pragma unroll
    for (int nt = 0; nt < 8; nt++){
        int col = nt*8 + c2;
        float b0 = __ldg(bias+col), b1 = __ldg(bias+col+1);
        float v0 = fmaxf(acc[nt][0]+b0, 0.f), v1 = fmaxf(acc[nt][1]+b1, 0.f);
        float v2 = fmaxf(acc[nt][2]+b0, 0.f), v3 = fmaxf(acc[nt][3]+b1, 0.f);
        uint32_t hp, lp;
        pack2(v0, v1, hp, lp);
        *(uint32_t*)(Hhi + (m0+r)*SA64*2 + col*2) = hp;
        *(uint32_t*)(Hlo + (m0+r)*SA64*2 + col*2) = lp;
        pack2(v2, v3, hp, lp);
        *(uint32_t*)(Hhi + (m0+r+8)*SA64*2 + col*2) = hp;
        *(uint32_t*)(Hlo + (m0+r+8)*SA64*2 + col*2) = lp;
    }
}
__device__ __forceinline__ void ln_pack_row(const float* sOut, int node, int row,
                                            const float* __restrict__ bias,
                                            const float* __restrict__ lg,
                                            const float* __restrict__ lb,
                                            char* Xhi, char* Xlo){
    float o[H];
#pragma unroll
    for (int i = 0; i < H; i++) o[i] = sOut[row*66 + i];
    const float4* xp = (const float4*)(g_x + (size_t)node * H);
#pragma unroll
    for (int i = 0; i < 16; i++){
        float4 f = xp[i];
        o[4*i+0] += f.x; o[4*i+1] += f.y; o[4*i+2] += f.z; o[4*i+3] += f.w;
    }
    if (bias){
#pragma unroll
        for (int i = 0; i < H; i++) o[i] += __ldg(&bias[i]);
    }
    float mean = 0.f;
#pragma unroll
    for (int i = 0; i < H; i++) mean += o[i];
    mean *= (1.f / H);
    float var = 0.f;
#pragma unroll
    for (int i = 0; i < H; i++){ float d = o[i] - mean; var += d * d; }
    var *= (1.f / H);
    float rr = rsqrtf(var + 1e-5f);
    float g[H];
#pragma unroll
    for (int i = 0; i < H; i++)
        g[i] = (o[i]-mean)*rr*__ldg(&lg[i]) + __ldg(&lb[i]);
    float4* op = (float4*)(g_x + (size_t)node * H);
#pragma unroll
    for (int i = 0; i < 16; i++)
        op[i] = make_float4(g[4*i+0], g[4*i+1], g[4*i+2], g[4*i+3]);
#pragma unroll
    for (int i = 0; i < 32; i++){
        uint32_t hp, lp;
        pack2(g[2*i], g[2*i+1], hp, lp);
        *(uint32_t*)(Xhi + row*SA64*2 + i*4) = hp;
        *(uint32_t*)(Xlo + row*SA64*2 + i*4) = lp;
    }
}
__device__ __forceinline__ void row_store_pack(const float* sOut, int node, int row,
                                               char* Xhi, char* Xlo){
    float g[H];
#pragma unroll
    for (int i = 0; i < H; i++) g[i] = sOut[row*66 + i];
    float4* op = (float4*)(g_x + (size_t)node * H);
#pragma unroll
    for (int i = 0; i < 16; i++)
        op[i] = make_float4(g[4*i+0], g[4*i+1], g[4*i+2], g[4*i+3]);
#pragma unroll
    for (int i = 0; i < 32; i++){
        uint32_t hp, lp;
        pack2(g[2*i], g[2*i+1], hp, lp);
        *(uint32_t*)(Xhi + row*SA64*2 + i*4) = hp;
        *(uint32_t*)(Xlo + row*SA64*2 + i*4) = lp;
    }
}

// ---------------- weight prep ----------------
__global__ void k_prep(const float* __restrict__ Win, const float* __restrict__ Wq,
                       const float* __restrict__ Wk, const float* __restrict__ Wv,
                       const float* __restrict__ Wo, const float* __restrict__ W1,
                       const float* __restrict__ W2){
    int t = blockIdx.x;
    const float* src; int ns, Ksrc;
    if (t == 0){ src = Win; ns = 64; Ksrc = FIN; }
    else {
        int l = (t-1)/8, j = (t-1)%8;
        if (j < 3){ const float* ws[3] = {Wq,Wk,Wv}; src = ws[j] + l*H*H; ns = 64; Ksrc = 64; }
        else if (j == 3){ src = Wo + l*H*H; ns = 64; Ksrc = 64; }
        else if (j < 6){ src = W1 + l*H*2*H + (j-4)*64; ns = 128; Ksrc = 64; }
        else { src = W2 + l*2*H*H + (j-6)*64*64; ns = 64; Ksrc = 64; }
    }
    char* dst = g_wimg + (size_t)t * TILE_B;
    for (int idx = threadIdx.x; idx < 64*32; idx += 256){
        int n = idx >> 5, p = idx & 31, k = 2*p;
        float v0 = (k   < Ksrc) ? __ldg(src + (size_t)k*ns + n)     : 0.f;
        float v1 = (k+1 < Ksrc) ? __ldg(src + (size_t)(k+1)*ns + n) : 0.f;
        uint32_t hp, lp;
        pack2(v0, v1, hp, lp);
        *(uint32_t*)(dst + n*SA64*2 + k*2) = hp;
        *(uint32_t*)(dst + B64_B + n*SA64*2 + k*2) = lp;
    }
}

// ---------------- CSR build (parallel scan) ----------------
__global__ void k_zero_deg(){
    int i = blockIdx.x * 256 + threadIdx.x;
    if (i < TOTN) g_deg[i] = 0;
}
__global__ void k_hist(const int* __restrict__ edst){
    int e = blockIdx.x * 256 + threadIdx.x;
    if (e < NEDGE) atomicAdd(&g_deg[edst[e]], 1);
}
__global__ __launch_bounds__(1024) void k_scan1(){
    __shared__ int s[1024];
    int tid = threadIdx.x;
    int i = blockIdx.x * 1024 + tid;
    int d = g_deg[i];
    s[tid] = d;
    __syncthreads();
#pragma unroll
    for (int off = 1; off < 1024; off <<= 1){
        int v = (tid >= off) ? s[tid - off] : 0;
        __syncthreads();
        s[tid] += v;
        __syncthreads();
    }
    g_rowptr[i] = s[tid] - d;
    if (tid == 1023) g_bsum[blockIdx.x] = s[1023];
}
__global__ void k_scan2(){
    if (threadIdx.x == 0){
        int run = 0;
        for (int b = 0; b < SCAN_BLKS; b++){ g_boff[b] = run; run += g_bsum[b]; }
        g_rowptr[TOTN] = run;
    }
}
__global__ __launch_bounds__(1024) void k_scan3(){
    int i = blockIdx.x * 1024 + threadIdx.x;
    int v = g_rowptr[i] + g_boff[blockIdx.x];
    g_rowptr[i] = v;
    g_cursor[i] = v;
}
__global__ void k_scatter(const int* __restrict__ esrc, const int* __restrict__ edst){
    int e = blockIdx.x * 256 + threadIdx.x;
    if (e < NEDGE){
        int d = edst[e];
        int pos = atomicAdd(&g_cursor[d], 1);
        g_srcs[pos] = esrc[e];
    }
}

// ---------------- fused input + layer-0 qkv (prefetched) ----------------
__global__ __launch_bounds__(NTHR) void k_in_qkv(const float* __restrict__ nf){
    extern __shared__ __align__(16) char sm[];
    char* Xhi = sm + R_X;   char* Xlo = Xhi + A64_B;
    char* B0  = sm + R_B0;
    char* Hhi = sm + R_H;   char* Hlo = Hhi + A64_B;
    char* B1  = sm + R_B1;
    int tid = threadIdx.x, wid = tid >> 5, lane = tid & 31;
    int node0 = blockIdx.x * BM;
    uint4 pf[PF_N];

    stage_A<FIN>(nf + (size_t)node0 * FIN, FIN, Hhi, Hlo, tid);
    stage_Bimg(0, B0, tid);
    __syncthreads();
    pref_ld(1, pf, tid);                       // q tile -> regs
    {
        float acc[8][4]; zero8(acc);
        mma_loop<2>(Hhi, Hlo, B0, lane, wid*16, acc);
        pref_st(B1, pf, tid);                  // drain q into B1
        __syncthreads();
        float* sOut = (float*)(sm + R_H);
        stage_frags8(sOut, wid*16, lane, acc);
        __syncthreads();
        if (tid < 128) row_store_pack(sOut, node0 + tid, tid, Xhi, Xlo);
        __syncthreads();
    }
    // qkv: q in B1, prefetch k,v alternating
    pref_ld(2, pf, tid);
    {
        float acc[8][4]; zero8(acc);
        mma_loop<4>(Xhi, Xlo, B1, lane, wid*16, acc);
        pref_st(B0, pf, tid);
        store_frags8(g_q + (size_t)node0 * H, H, wid*16, lane, acc);
        __syncthreads();
    }
    pref_ld(3, pf, tid);
    {
        float acc[8][4]; zero8(acc);
        mma_loop<4>(Xhi, Xlo, B0, lane, wid*16, acc);
        pref_st(B1, pf, tid);
        store_frags8(g_k + (size_t)node0 * H, H, wid*16, lane, acc);
        __syncthreads();
    }
    {
        float acc[8][4]; zero8(acc);
        mma_loop<4>(Xhi, Xlo, B1, lane, wid*16, acc);
        store_frags8(g_v + (size_t)node0 * H, H, wid*16, lane, acc);
    }
}

// ---------------- fused layer (prefetched) ----------------
__global__ __launch_bounds__(NTHR) void k_layer(int l,
                                                const float* __restrict__ lg1,
                                                const float* __restrict__ lb1,
                                                const float* __restrict__ b1,
                                                const float* __restrict__ b2,
                                                const float* __restrict__ lg2,
                                                const float* __restrict__ lb2,
                                                int last){
    extern __shared__ __align__(16) char sm[];
    char* Xhi = sm + R_X;   char* Xlo = Xhi + A64_B;
    char* B0  = sm + R_B0;
    char* Hhi = sm + R_H;   char* Hlo = Hhi + A64_B;
    char* B1  = sm + R_B1;
    int tid = threadIdx.x, wid = tid >> 5, lane = tid & 31;
    int node0 = blockIdx.x * BM;
    int tb = 1 + l*8;
    uint4 pf[PF_N];

    // phase 1: Wo in B0; prefetch W1a during mma
    stage_A<H>(g_agg + (size_t)node0 * H, H, Hhi, Hlo, tid);
    stage_Bimg(tb + 3, B0, tid);
    __syncthreads();
    pref_ld(tb + 4, pf, tid);                  // W1a
    {
        float acc[8][4]; zero8(acc);
        mma_loop<4>(Hhi, Hlo, B0, lane, wid*16, acc);
        pref_st(B1, pf, tid);
        __syncthreads();
        float* sOut = (float*)(sm + R_H);
        stage_frags8(sOut, wid*16, lane, acc);
        __syncthreads();
        if (tid < 128) ln_pack_row(sOut, node0 + tid, tid, nullptr, lg1, lb1, Xhi, Xlo);
        __syncthreads();
    }

    // phase 2: h=0 (W1a in B1)
    float acc2[8][4]; zero8(acc2);
    pref_ld(tb + 6, pf, tid);                  // W2a
    {
        float acc[8][4]; zero8(acc);
        mma_loop<4>(Xhi, Xlo, B1, lane, wid*16, acc);
        pref_st(B0, pf, tid);
        __syncthreads();
        frag_relu_pack(Hhi, Hlo, wid*16, lane, acc, b1);
        __syncthreads();
    }
    pref_ld(tb + 5, pf, tid);                  // W1b
    mma_loop<4>(Hhi, Hlo, B0, lane, wid*16, acc2);
    pref_st(B1, pf, tid);
    __syncthreads();
    // h=1 (W1b in B1)
    pref_ld(tb + 7, pf, tid);                  // W2b
    {
        float acc[8][4]; zero8(acc);
        mma_loop<4>(Xhi, Xlo, B1, lane, wid*16, acc);
        pref_st(B0, pf, tid);
        __syncthreads();
        frag_relu_pack(Hhi, Hlo, wid*16, lane, acc, b1 + 64);
        __syncthreads();
    }
    if (!last) pref_ld(tb + 8, pf, tid);       // next-layer q
    mma_loop<4>(Hhi, Hlo, B0, lane, wid*16, acc2);
    if (!last) pref_st(B1, pf, tid);
    __syncthreads();

    // phase 3: x = LN2(x + h@W2 + b2)
    {
        float* sOut = (float*)(sm + R_H);
        stage_frags8(sOut, wid*16, lane, acc2);
        __syncthreads();
        if (tid < 128) ln_pack_row(sOut, node0 + tid, tid, b2, lg2, lb2, Xhi, Xlo);
        __syncthreads();
    }

    // phase 4: qkv for next layer (q in B1)
    if (!last){
        pref_ld(tb + 9, pf, tid);              // k
        {
            float acc[8][4]; zero8(acc);
            mma_loop<4>(Xhi, Xlo, B1, lane, wid*16, acc);
            pref_st(B0, pf, tid);
            store_frags8(g_q + (size_t)node0 * H, H, wid*16, lane, acc);
            __syncthreads();
        }
        pref_ld(tb + 10, pf, tid);             // v
        {
            float acc[8][4]; zero8(acc);
            mma_loop<4>(Xhi, Xlo, B0, lane, wid*16, acc);
            pref_st(B1, pf, tid);
            store_frags8(g_k + (size_t)node0 * H, H, wid*16, lane, acc);
            __syncthreads();
        }
        {
            float acc[8][4]; zero8(acc);
            mma_loop<4>(Xhi, Xlo, B1, lane, wid*16, acc);
            store_frags8(g_v + (size_t)node0 * H, H, wid*16, lane, acc);
        }
    }
}

// ---------------- warp-per-node attention (online softmax) ----------------
__global__ __launch_bounds__(256) void k_attn(){
    int warp = (blockIdx.x * 256 + threadIdx.x) >> 5;
    int lane = threadIdx.x & 31;
    if (warp >= TOTN) return;
    int node = warp;
    float2 q = *(const float2*)(g_q + (size_t)node * H + 2*lane);
    int s0 = g_rowptr[node], s1 = g_rowptr[node + 1];
    float m = -1e30f, den = 0.f, ax = 0.f, ay = 0.f;
    for (int e = s0; e < s1; e++){
        int src = g_srcs[e];
        float2 kk = *(const float2*)(g_k + (size_t)src * H + 2*lane);
        float2 vv = *(const float2*)(g_v + (size_t)src * H + 2*lane);
        float p = q.x * kk.x + q.y * kk.y;
        p += __shfl_xor_sync(0xffffffffu, p, 1);
        p += __shfl_xor_sync(0xffffffffu, p, 2);
        p += __shfl_xor_sync(0xffffffffu, p, 4);
        float s = p * 0.25f;
        float mn = fmaxf(m, s);
        float scale = __expf(m - mn);
        float w = __expf(s - mn);
        den = den * scale + w;
        ax = ax * scale + w * vv.x;
        ay = ay * scale + w * vv.y;
        m = mn;
    }
    float inv = 1.f / (den + 1e-9f);
    *(float2*)(g_agg + (size_t)node * H + 2*lane) = make_float2(ax * inv, ay * inv);
}

// ---------------- merged heads ----------------
__global__ __launch_bounds__(512) void k_heads(const int* __restrict__ an,
                                               const float* __restrict__ obs,
                                               const float* __restrict__ Wr,  const float* __restrict__ br,
                                               const float* __restrict__ Wp1, const float* __restrict__ bp1,
                                               const float* __restrict__ Wp2, const float* __restrict__ bp2,
                                               const float* __restrict__ Wlog,const float* __restrict__ blog,
                                               const float* __restrict__ Wv1, const float* __restrict__ bv1,
                                               const float* __restrict__ Wv2, const float* __restrict__ bv2,
                                               const float* __restrict__ Wvo, const float* __restrict__ bvo,
                                               float* __restrict__ out){
    __shared__ float sr[ACT + OBSD];
    __shared__ float sx[H];
    __shared__ float sfeat[HS];
    __shared__ float svh[VHD];
    __shared__ float sval[1];
    int b = blockIdx.x;
    int tid = threadIdx.x;

    if (tid == 0) sval[0] = 0.f;          // init before first barrier
    if (tid < H) sx[tid] = g_x[(size_t)an[b] * H + tid];
    for (int i = tid; i < OBSD; i += 512) sr[ACT + i] = obs[(size_t)b * OBSD + i];
    __syncthreads();
    if (tid < ACT){
        float acc = br[tid];
        for (int i = 0; i < H; i++) acc += sx[i] * __ldg(&Wr[i*ACT + tid]);
        sr[tid] = acc;
    }
    __syncthreads();
    if (tid < VHD){
        const float* W = Wv1 + tid;
        float a0 = 0, a1 = 0, a2 = 0, a3 = 0;
        for (int i = 0; i < OBSD; i += 4){
            a0 += sr[ACT+i+0] * W[(size_t)(i+0)*VHD];
            a1 += sr[ACT+i+1] * W[(size_t)(i+1)*VHD];
            a2 += sr[ACT+i+2] * W[(size_t)(i+2)*VHD];
            a3 += sr[ACT+i+3] * W[(size_t)(i+3)*VHD];
        }
        svh[tid] = tanhf(a0 + a1 + a2 + a3 + bv1[tid]);
    }
    {
        int j = tid;
        const float* W = Wp1 + j;
        float a0 = 0, a1 = 0, a2 = 0, a3 = 0;
        int i = 0;
        const int K = ACT + OBSD;
        for (; i + 3 < K; i += 4){
            a0 += sr[i+0] * W[(size_t)(i+0)*HS];
            a1 += sr[i+1] * W[(size_t)(i+1)*HS];
            a2 += sr[i+2] * W[(size_t)(i+2)*HS];
            a3 += sr[i+3] * W[(size_t)(i+3)*HS];
        }
        for (; i < K; i++) a0 += sr[i] * W[(size_t)i*HS];
        float f = tanhf(a0 + a1 + a2 + a3 + bp1[j]);
        __syncthreads();
        sfeat[j] = f;
    }
    __syncthreads();
    if (tid < VHD){
        const float* W = Wv2 + tid;
        float a0 = 0, a1 = 0, a2 = 0, a3 = 0;
        for (int i = 0; i < VHD; i += 4){
            a0 += svh[i+0] * W[(i+0)*VHD];
            a1 += svh[i+1] * W[(i+1)*VHD];
            a2 += svh[i+2] * W[(i+2)*VHD];
            a3 += svh[i+3] * W[(i+3)*VHD];
        }
        float vh2 = tanhf(a0 + a1 + a2 + a3 + bv2[tid]);
        float p = vh2 * __ldg(&Wvo[tid]);
        p += __shfl_xor_sync(0xffffffffu, p, 1);
        p += __shfl_xor_sync(0xffffffffu, p, 2);
        p += __shfl_xor_sync(0xffffffffu, p, 4);
        p += __shfl_xor_sync(0xffffffffu, p, 8);
        p += __shfl_xor_sync(0xffffffffu, p, 16);
        if ((tid & 31) == 0) atomicAdd(&sval[0], p);
    }
    {
        int j = tid;
        const float* W = Wp2 + j;
        float a0 = 0, a1 = 0, a2 = 0, a3 = 0;
        for (int i = 0; i < HS; i += 4){
            a0 += sfeat[i+0] * W[(size_t)(i+0)*HS];
            a1 += sfeat[i+1] * W[(size_t)(i+1)*HS];
            a2 += sfeat[i+2] * W[(size_t)(i+2)*HS];
            a3 += sfeat[i+3] * W[(size_t)(i+3)*HS];
        }
        float f2 = tanhf(a0 + a1 + a2 + a3 + bp2[j]);
        __syncthreads();
        sfeat[j] = f2;
    }
    __syncthreads();
    if (tid < NOUTD){
        float acc = blog[tid];
        for (int i = 0; i < HS; i++) acc += sfeat[i] * __ldg(&Wlog[i*NOUTD + tid]);
        out[b*NOUTD + tid] = acc;
    }
    if (tid == 0) out[BATCH*NOUTD + b] = sval[0] + bvo[0];
}

// ---------------- launch ----------------
extern "C" void kernel_launch(void* const* d_in, const int* in_sizes, int n_in,
                              void* d_out, int out_size){
    const float* node_feats = (const float*)d_in[0];
    const float* obs        = (const float*)d_in[1];
    const int*   edge_src   = (const int*)  d_in[2];
    const int*   edge_dst   = (const int*)  d_in[3];
    const int*   agent      = (const int*)  d_in[4];
    const float* W_in  = (const float*)d_in[5];
    const float* Wq    = (const float*)d_in[6];
    const float* Wk    = (const float*)d_in[7];
    const float* Wv    = (const float*)d_in[8];
    const float* Wo    = (const float*)d_in[9];
    const float* ln1g  = (const float*)d_in[10];
    const float* ln1b  = (const float*)d_in[11];
    const float* W1    = (const float*)d_in[12];
    const float* b1    = (const float*)d_in[13];
    const float* W2    = (const float*)d_in[14];
    const float* b2    = (const float*)d_in[15];
    const float* ln2g  = (const float*)d_in[16];
    const float* ln2b  = (const float*)d_in[17];
    const float* Wr    = (const float*)d_in[18];
    const float* br    = (const float*)d_in[19];
    const float* Wp1   = (const float*)d_in[20];
    const float* bp1   = (const float*)d_in[21];
    const float* Wp2   = (const float*)d_in[22];
    const float* bp2   = (const float*)d_in[23];
    const float* Wlog  = (const float*)d_in[24];
    const float* blog  = (const float*)d_in[25];
    const float* Wv1   = (const float*)d_in[26];
    const float* bv1   = (const float*)d_in[27];
    const float* Wv2   = (const float*)d_in[28];
    const float* bv2   = (const float*)d_in[29];
    const float* Wvo   = (const float*)d_in[30];
    const float* bvo   = (const float*)d_in[31];
    float* out = (float*)d_out;

    cudaFuncSetAttribute((const void*)k_in_qkv, cudaFuncAttributeMaxDynamicSharedMemorySize, SM_LAYER);
    cudaFuncSetAttribute((const void*)k_layer,  cudaFuncAttributeMaxDynamicSharedMemorySize, SM_LAYER);

    k_prep<<<NTILES, 256>>>(W_in, Wq, Wk, Wv, Wo, W1, W2);
    k_zero_deg<<<(TOTN + 255)/256, 256>>>();
    k_hist<<<(NEDGE + 255)/256, 256>>>(edge_dst);
    k_in_qkv<<<NB, NTHR, SM_LAYER>>>(node_feats);      // capture slot (index 3)
    k_scan1<<<SCAN_BLKS, 1024>>>();
    k_scan2<<<1, 32>>>();
    k_scan3<<<SCAN_BLKS, 1024>>>();
    k_scatter<<<(NEDGE + 255)/256, 256>>>(edge_src, edge_dst);

    for (int l = 0; l < LAYERS; l++){
        k_attn<<<(TOTN*32 + 255)/256, 256>>>();
        k_layer<<<NB, NTHR, SM_LAYER>>>(l, ln1g + l*H, ln1b + l*H,
                                        b1 + l*2*H, b2 + l*H,
                                        ln2g + l*H, ln2b + l*H,
                                        (l == LAYERS-1) ? 1 : 0);
    }

    k_heads<<<BATCH, 512>>>(agent, obs, Wr, br, Wp1, bp1, Wp2, bp2,
                            Wlog, blog, Wv1, bv1, Wv2, bv2, Wvo, bvo, out);
}